// round 13
// baseline (speedup 1.0000x reference)
#include <cuda_runtime.h>
#include <cuda_bf16.h>
#include <cstdint>

#define BATCHN 1024
#define NIMG   2048

// ---- smem layout (bytes) ----
#define SM_Z     0          // z hi 8192 + z lo 8192 bf16, swizzled (one 32-row chunk)
#define SM_UHI   16384      // u hi bf16 [a][m], stride 272B x 128 rows (34816)
#define SM_ULO   51200      // u lo
#define SMEM_TOTAL 86016

typedef unsigned int u32;

// fragment tables (precomputed by setup kernel)
__device__ __align__(16) uint4 g_FXfrag[8 * 8 * 32];       // (j,s,lane): {b0h,b1h,b0l,b1l}
__device__ __align__(16) uint4 g_FYfrag[4 * 8 * 32 * 2];   // ((r,s,lane)*2+{hi,lo}): {a0,a1,a2,a3}

// ======================= helpers =======================
__device__ __forceinline__ u32 prmt_hi(u32 a, u32 b) {   // low16=a.hi16, high16=b.hi16
    u32 r;
    asm("prmt.b32 %0, %1, %2, 0x7632;" : "=r"(r) : "r"(a), "r"(b));
    return r;
}
__device__ __forceinline__ u32 pack_lo2(float e0, float e1) {   // low16=bf16(e0), high16=bf16(e1)
    u32 r;
    asm("cvt.rn.bf16x2.f32 %0, %1, %2;" : "=r"(r) : "f"(e1), "f"(e0));
    return r;
}
__device__ __forceinline__ float hif(float x) {
    return __uint_as_float(__float_as_uint(x) & 0xFFFF0000u);
}
__device__ __forceinline__ u32 zswz(int row, int seg) {   // byte offset in 32x256B plane
    return (u32)(row * 256 + ((seg ^ (row & 7) ^ (((row >> 3) & 1) << 3)) << 4));
}

// ======================= setup kernel =======================
__global__ void setup_kernel(const float* __restrict__ hrow,
                             const float* __restrict__ W,
                             const float* __restrict__ bias) {
    __shared__ float red[256];
    __shared__ float sc[8];
    int tid = threadIdx.x;

    for (int j = 0; j < 5; j++) {
        float s = 0.f;
        for (int k = tid; k < 1024; k += 256) s += hrow[k] * W[j * 1024 + k];
        red[tid] = s; __syncthreads();
        for (int o = 128; o > 0; o >>= 1) { if (tid < o) red[tid] += red[tid + o]; __syncthreads(); }
        if (tid == 0) sc[j] = red[0] + bias[j];
        __syncthreads();
    }

    if (tid == 0) {
        float gtX = sc[0], gtY = sc[1], log_var = sc[2], log_dt = sc[3], lg = sc[4];
        sc[0] = 129.f * (gtX + 1.f) * 0.5f;
        sc[1] = 129.f * (gtY + 1.f) * 0.5f;
        sc[2] = expf(log_var + 1e-8f);
        sc[3] = expf(log_dt) * (127.f / 63.f);
        sc[4] = expf(lg);
    }
    __syncthreads();
    float gX = sc[0], gY = sc[1], var = sc[2], dd = sc[3], gamma = sc[4];
    float inv2v = 1.0f / (2.0f * var);

    float pY = 0.f, pX = 0.f;
    for (int idx = tid; idx < 8192; idx += 256) {
        int n = idx >> 7, c = idx & 127;
        float dY = (float)c - (gY + ((float)n - 32.5f) * dd);
        pY += expf(-dY * dY * inv2v);
        float dX = (float)c - (gX + ((float)n - 32.5f) * dd);
        pX += expf(-dX * dX * inv2v);
    }
    red[tid] = pY; __syncthreads();
    for (int o = 128; o > 0; o >>= 1) { if (tid < o) red[tid] += red[tid + o]; __syncthreads(); }
    if (tid == 0) sc[5] = red[0];
    __syncthreads();
    red[tid] = pX; __syncthreads();
    for (int o = 128; o > 0; o >>= 1) { if (tid < o) red[tid] += red[tid + o]; __syncthreads(); }
    if (tid == 0) sc[6] = red[0];
    __syncthreads();

    float sY = gamma / sc[5];
    float sX = 1.0f / sc[6];

    // FX B-fragments
    for (int e = tid; e < 2048; e += 256) {
        int lane = e & 31, s = (e >> 5) & 7, j = e >> 8;
        int gid = lane >> 2, t4 = lane & 3;
        int m = 8 * j + gid;
        float mu = gX + ((float)m - 32.5f) * dd;
        int b0 = 16 * s + t4 * 2;
        float d0 = (float)b0 - mu,       d1 = (float)(b0 + 1) - mu;
        float d2 = (float)(b0 + 8) - mu, d3 = (float)(b0 + 9) - mu;
        float x0 = expf(-d0 * d0 * inv2v) * sX;
        float x1 = expf(-d1 * d1 * inv2v) * sX;
        float x2 = expf(-d2 * d2 * inv2v) * sX;
        float x3 = expf(-d3 * d3 * inv2v) * sX;
        uint4 v;
        v.x = prmt_hi(__float_as_uint(x0), __float_as_uint(x1));
        v.y = prmt_hi(__float_as_uint(x2), __float_as_uint(x3));
        v.z = pack_lo2(x0 - hif(x0), x1 - hif(x1));
        v.w = pack_lo2(x2 - hif(x2), x3 - hif(x3));
        g_FXfrag[e] = v;
    }

    // FY A-fragments
    for (int e = tid; e < 1024; e += 256) {
        int lane = e & 31, s = (e >> 5) & 7, r = e >> 8;
        int gid = lane >> 2, t4 = lane & 3;
        int n0 = 16 * r + gid, n1 = n0 + 8;
        float mu0 = gY + ((float)n0 - 32.5f) * dd;
        float mu1 = gY + ((float)n1 - 32.5f) * dd;
        int a0 = 16 * s + t4 * 2;
        float y[8];
        y[0] = expf(-((float)a0 - mu0)     * ((float)a0 - mu0)     * inv2v) * sY;
        y[1] = expf(-((float)(a0+1) - mu0) * ((float)(a0+1) - mu0) * inv2v) * sY;
        y[2] = expf(-((float)a0 - mu1)     * ((float)a0 - mu1)     * inv2v) * sY;
        y[3] = expf(-((float)(a0+1) - mu1) * ((float)(a0+1) - mu1) * inv2v) * sY;
        y[4] = expf(-((float)(a0+8) - mu0) * ((float)(a0+8) - mu0) * inv2v) * sY;
        y[5] = expf(-((float)(a0+9) - mu0) * ((float)(a0+9) - mu0) * inv2v) * sY;
        y[6] = expf(-((float)(a0+8) - mu1) * ((float)(a0+8) - mu1) * inv2v) * sY;
        y[7] = expf(-((float)(a0+9) - mu1) * ((float)(a0+9) - mu1) * inv2v) * sY;
        uint4 hi, lo;
        hi.x = prmt_hi(__float_as_uint(y[0]), __float_as_uint(y[1]));
        hi.y = prmt_hi(__float_as_uint(y[2]), __float_as_uint(y[3]));
        hi.z = prmt_hi(__float_as_uint(y[4]), __float_as_uint(y[5]));
        hi.w = prmt_hi(__float_as_uint(y[6]), __float_as_uint(y[7]));
        lo.x = pack_lo2(y[0] - hif(y[0]), y[1] - hif(y[1]));
        lo.y = pack_lo2(y[2] - hif(y[2]), y[3] - hif(y[3]));
        lo.z = pack_lo2(y[4] - hif(y[4]), y[5] - hif(y[5]));
        lo.w = pack_lo2(y[6] - hif(y[6]), y[7] - hif(y[7]));
        g_FYfrag[2 * e]     = hi;
        g_FYfrag[2 * e + 1] = lo;
    }
}

// ======================= device helpers =======================
__device__ __forceinline__ u32 smem_u32(const void* p) {
    u32 a;
    asm("{ .reg .u64 t; cvta.to.shared.u64 t, %1; cvt.u32.u64 %0, t; }" : "=r"(a) : "l"(p));
    return a;
}
__device__ __forceinline__ void ldm_x4(u32& r0, u32& r1, u32& r2, u32& r3, u32 addr) {
    asm volatile("ldmatrix.sync.aligned.m8n8.x4.shared.b16 {%0,%1,%2,%3}, [%4];"
                 : "=r"(r0), "=r"(r1), "=r"(r2), "=r"(r3) : "r"(addr));
}
__device__ __forceinline__ void ldm_x4t(u32& r0, u32& r1, u32& r2, u32& r3, u32 addr) {
    asm volatile("ldmatrix.sync.aligned.m8n8.x4.trans.shared.b16 {%0,%1,%2,%3}, [%4];"
                 : "=r"(r0), "=r"(r1), "=r"(r2), "=r"(r3) : "r"(addr));
}
__device__ __forceinline__ void mma_bf16(float* c, u32 a0, u32 a1, u32 a2, u32 a3, u32 b0, u32 b1) {
    asm volatile(
        "mma.sync.aligned.m16n8k16.row.col.f32.bf16.bf16.f32 "
        "{%0,%1,%2,%3}, {%4,%5,%6,%7}, {%8,%9}, {%0,%1,%2,%3};"
        : "+f"(c[0]), "+f"(c[1]), "+f"(c[2]), "+f"(c[3])
        : "r"(a0), "r"(a1), "r"(a2), "r"(a3), "r"(b0), "r"(b1));
}

// direct global load of one 32-row chunk slice into registers (coalesced LDG.128)
__device__ __forceinline__ void load_v(const float* __restrict__ x,
                                       const float* __restrict__ xh,
                                       int img, int c, int tid, float* v) {
    const float* b = (img < BATCHN) ? x + (size_t)img * 16384
                                    : xh + (size_t)(img - BATCHN) * 16384;
    const float* zr = b + c * 4096 + (tid >> 3) * 128 + (tid & 7) * 16;
    *(float4*)(v)      = __ldg((const float4*)(zr));
    *(float4*)(v + 4)  = __ldg((const float4*)(zr + 4));
    *(float4*)(v + 8)  = __ldg((const float4*)(zr + 8));
    *(float4*)(v + 12) = __ldg((const float4*)(zr + 12));
}
// convert registers -> z bf16 hi/lo planes (swizzled)
__device__ __forceinline__ void conv_store(char* smem, int tid, const float* v) {
    u32 H[8], L[8];
#pragma unroll
    for (int p = 0; p < 8; p++) {
        u32 b0 = __float_as_uint(v[2 * p]), b1 = __float_as_uint(v[2 * p + 1]);
        H[p] = prmt_hi(b0, b1);
        L[p] = pack_lo2(v[2 * p]     - __uint_as_float(b0 & 0xFFFF0000u),
                        v[2 * p + 1] - __uint_as_float(b1 & 0xFFFF0000u));
    }
    int r = tid >> 3, j8 = tid & 7;
    u32 o0 = zswz(r, 2 * j8), o1 = zswz(r, 2 * j8 + 1);
    *(uint4*)(smem + SM_Z + o0)        = make_uint4(H[0], H[1], H[2], H[3]);
    *(uint4*)(smem + SM_Z + o1)        = make_uint4(H[4], H[5], H[6], H[7]);
    *(uint4*)(smem + SM_Z + 8192 + o0) = make_uint4(L[0], L[1], L[2], L[3]);
    *(uint4*)(smem + SM_Z + 8192 + o1) = make_uint4(L[4], L[5], L[6], L[7]);
}

// ======================= main kernel =======================
__global__ void __launch_bounds__(256, 2)
main_kernel(const float* __restrict__ x, const float* __restrict__ xh,
            float* __restrict__ out, int grid) {
    extern __shared__ __align__(16) char smem[];
    int tid = threadIdx.x, wid = tid >> 5, lid = tid & 31;
    int gid = lid >> 2, t4 = lid & 3;

    u32 base = smem_u32(smem);

    // stage-1 warp mapping: ablock = wid>>2 (16 a-rows within chunk), nq = wid&3 (2 m-tiles)
    int ablock = wid >> 2, nq = wid & 3;
    // fxA persistent in registers; fxB streamed from L1 per k-step
    uint4 fxA[8];
#pragma unroll
    for (int s = 0; s < 8; s++)
        fxA[s] = __ldg(&g_FXfrag[((2 * nq) * 8 + s) * 32 + lid]);
    const uint4* fxBp = &g_FXfrag[(2 * nq + 1) * 8 * 32 + lid];

    int rowA = ablock * 16 + (lid & 7) + ((lid >> 3) & 1) * 8;
    int segb = lid >> 4;
    // stage-2 mapping (x4t: lanes 0-15 -> UHI rows, 16-31 -> ULO rows)
    int r2 = wid >> 1, jh = wid & 1;
    int rowk = lid & 15, half = lid >> 4;
    u32 u_lane = base + (half ? SM_ULO : SM_UHI) + (u32)rowk * 272;

    int img0 = blockIdx.x;

    // prologue: load chunk 0 of first image
    float v[16];
    if (img0 < NIMG) load_v(x, xh, img0, 0, tid, v);

    for (int img = img0; img < NIMG; img += grid) {

        // ================= stage 1: four 32-row chunks =================
#pragma unroll 1
        for (int c = 0; c < 4; c++) {
            // convert prefetched registers into z planes
            conv_store(smem, tid, v);
            __syncthreads();

            // prefetch next chunk (next image's chunk 0 when c==3)
            {
                int nimg = (c < 3) ? img : img + grid;
                int nc   = (c < 3) ? c + 1 : 0;
                if (nimg < NIMG) load_v(x, xh, nimg, nc, tid, v);
            }

            // ---- MMA chunk c ----
            float acc0[4] = {0.f, 0.f, 0.f, 0.f};
            float acc1[4] = {0.f, 0.f, 0.f, 0.f};
#pragma unroll
            for (int s = 0; s < 8; s++) {
                u32 sw = zswz(rowA, 2 * s + segb);
                u32 h0, h1, h2, h3, l0, l1, l2, l3;
                ldm_x4(h0, h1, h2, h3, base + SM_Z + sw);
                ldm_x4(l0, l1, l2, l3, base + SM_Z + 8192 + sw);
                uint4 fxB = __ldg(fxBp + s * 32);
                mma_bf16(acc0, h0, h1, h2, h3, fxA[s].x, fxA[s].y);   // hh A
                mma_bf16(acc1, h0, h1, h2, h3, fxB.x,    fxB.y);      // hh B
                mma_bf16(acc0, h0, h1, h2, h3, fxA[s].z, fxA[s].w);   // hl A
                mma_bf16(acc1, h0, h1, h2, h3, fxB.z,    fxB.w);      // hl B
                mma_bf16(acc0, l0, l1, l2, l3, fxA[s].x, fxA[s].y);   // lh A
                mma_bf16(acc1, l0, l1, l2, l3, fxB.x,    fxB.y);      // lh B
            }

            // ---- u epilogue: rows -> bf16 hi/lo, stride 272 B ----
            {
                int ag0 = c * 32 + ablock * 16 + gid;      // rows ag0, ag0+8
#pragma unroll
                for (int jj = 0; jj < 2; jj++) {
                    const float* A = jj ? acc1 : acc0;
                    int m = 8 * (2 * nq + jj) + t4 * 2;
                    u32 h0 = prmt_hi(__float_as_uint(A[0]), __float_as_uint(A[1]));
                    u32 l0 = pack_lo2(A[0] - hif(A[0]), A[1] - hif(A[1]));
                    u32 h1 = prmt_hi(__float_as_uint(A[2]), __float_as_uint(A[3]));
                    u32 l1 = pack_lo2(A[2] - hif(A[2]), A[3] - hif(A[3]));
                    *(u32*)(smem + SM_UHI + ag0 * 272 + m * 2)       = h0;
                    *(u32*)(smem + SM_UHI + (ag0 + 8) * 272 + m * 2) = h1;
                    *(u32*)(smem + SM_ULO + ag0 * 272 + m * 2)       = l0;
                    *(u32*)(smem + SM_ULO + (ag0 + 8) * 272 + m * 2) = l1;
                }
            }
            __syncthreads();   // z plane free for next convert; after c==3: u complete
        }

        // ================= stage 2: out = FY @ u =================
        float a2[4][4];
#pragma unroll
        for (int jj = 0; jj < 4; jj++)
#pragma unroll
            for (int q = 0; q < 4; q++) a2[jj][q] = 0.f;

#pragma unroll
        for (int s = 0; s < 8; s++) {
            uint4 fyh = __ldg(&g_FYfrag[((r2 * 8 + s) * 32 + lid) * 2]);
            uint4 fyl = __ldg(&g_FYfrag[((r2 * 8 + s) * 32 + lid) * 2 + 1]);
            u32 soff = (u32)(s * 16 * 272);
#pragma unroll
            for (int jj = 0; jj < 4; jj++) {
                int j = jh * 4 + jj;
                u32 bh0, bh1, bl0, bl1;
                ldm_x4t(bh0, bh1, bl0, bl1, u_lane + soff + j * 16);
                mma_bf16(a2[jj], fyh.x, fyh.y, fyh.z, fyh.w, bh0, bh1);   // hh
                mma_bf16(a2[jj], fyh.x, fyh.y, fyh.z, fyh.w, bl0, bl1);   // hl
                mma_bf16(a2[jj], fyl.x, fyl.y, fyl.z, fyl.w, bh0, bh1);   // lh
            }
        }

        // ---- write out ----
        size_t obase = (img < BATCHN) ? (size_t)img * 8192
                                      : (size_t)(img - BATCHN) * 8192 + 4096;
        float* op = out + obase;
        int n0 = 16 * r2 + gid;
#pragma unroll
        for (int jj = 0; jj < 4; jj++) {
            int m = 8 * (jh * 4 + jj) + t4 * 2;
            float2 v0; v0.x = a2[jj][0]; v0.y = a2[jj][1];
            float2 v1; v1.x = a2[jj][2]; v1.y = a2[jj][3];
            *(float2*)(op + (size_t)n0 * 64 + m)       = v0;
            *(float2*)(op + (size_t)(n0 + 8) * 64 + m) = v1;
        }
        __syncthreads();   // u free before next image's stage-1 u-stores
    }
}

// ======================= launch =======================
extern "C" void kernel_launch(void* const* d_in, const int* in_sizes, int n_in,
                              void* d_out, int out_size) {
    const float* x  = (const float*)d_in[0];
    const float* xh = (const float*)d_in[1];
    const float* h  = (const float*)d_in[2];
    const float* W  = (const float*)d_in[3];
    const float* b  = (const float*)d_in[4];
    float* out = (float*)d_out;

    setup_kernel<<<1, 256>>>(h, W, b);

    cudaFuncSetAttribute(main_kernel, cudaFuncAttributeMaxDynamicSharedMemorySize, SMEM_TOTAL);

    int dev = 0, sm = 148;
    cudaGetDevice(&dev);
    cudaDeviceGetAttribute(&sm, cudaDevAttrMultiProcessorCount, dev);
    int grid = 2 * sm;              // 2 CTAs per SM
    if (grid < 2) grid = 296;
    if (grid > NIMG) grid = NIMG;

    main_kernel<<<grid, 256, SMEM_TOTAL>>>(x, xh, out, grid);
}

// round 14
// speedup vs baseline: 1.1678x; 1.1678x over previous
#include <cuda_runtime.h>
#include <cuda_bf16.h>
#include <cstdint>

#define BATCHN 1024
#define NIMG   2048

// ---- smem layout (bytes) ----
#define SM_Z     0          // superchunk z: hi 16384 (64x256B) + lo 16384, swizzled
#define SM_UHI   32768      // u hi bf16 [a][m], stride 272B x 128 rows (34816)
#define SM_ULO   67584      // u lo
#define SMEM_TOTAL 102400

typedef unsigned int u32;

// fragment tables (precomputed by setup kernel)
__device__ __align__(16) uint4 g_FXfrag[8 * 8 * 32];       // (j,s,lane): {b0h,b1h,b0l,b1l}
__device__ __align__(16) uint4 g_FYfrag[4 * 8 * 32 * 2];   // ((r,s,lane)*2+{hi,lo}): {a0,a1,a2,a3}

// ======================= helpers =======================
__device__ __forceinline__ u32 prmt_hi(u32 a, u32 b) {   // low16=a.hi16, high16=b.hi16
    u32 r;
    asm("prmt.b32 %0, %1, %2, 0x7632;" : "=r"(r) : "r"(a), "r"(b));
    return r;
}
__device__ __forceinline__ u32 pack_lo2(float e0, float e1) {   // low16=bf16(e0), high16=bf16(e1)
    u32 r;
    asm("cvt.rn.bf16x2.f32 %0, %1, %2;" : "=r"(r) : "f"(e1), "f"(e0));
    return r;
}
__device__ __forceinline__ float hif(float x) {
    return __uint_as_float(__float_as_uint(x) & 0xFFFF0000u);
}
__device__ __forceinline__ u32 zswz(int row, int seg) {   // byte offset in 64x256B plane
    return (u32)(row * 256 + ((seg ^ (row & 7) ^ (((row >> 3) & 1) << 3)) << 4));
}

// ======================= setup kernel =======================
__global__ void setup_kernel(const float* __restrict__ hrow,
                             const float* __restrict__ W,
                             const float* __restrict__ bias) {
    __shared__ float red[256];
    __shared__ float sc[8];
    int tid = threadIdx.x;

    for (int j = 0; j < 5; j++) {
        float s = 0.f;
        for (int k = tid; k < 1024; k += 256) s += hrow[k] * W[j * 1024 + k];
        red[tid] = s; __syncthreads();
        for (int o = 128; o > 0; o >>= 1) { if (tid < o) red[tid] += red[tid + o]; __syncthreads(); }
        if (tid == 0) sc[j] = red[0] + bias[j];
        __syncthreads();
    }

    if (tid == 0) {
        float gtX = sc[0], gtY = sc[1], log_var = sc[2], log_dt = sc[3], lg = sc[4];
        sc[0] = 129.f * (gtX + 1.f) * 0.5f;
        sc[1] = 129.f * (gtY + 1.f) * 0.5f;
        sc[2] = expf(log_var + 1e-8f);
        sc[3] = expf(log_dt) * (127.f / 63.f);
        sc[4] = expf(lg);
    }
    __syncthreads();
    float gX = sc[0], gY = sc[1], var = sc[2], dd = sc[3], gamma = sc[4];
    float inv2v = 1.0f / (2.0f * var);

    float pY = 0.f, pX = 0.f;
    for (int idx = tid; idx < 8192; idx += 256) {
        int n = idx >> 7, c = idx & 127;
        float dY = (float)c - (gY + ((float)n - 32.5f) * dd);
        pY += expf(-dY * dY * inv2v);
        float dX = (float)c - (gX + ((float)n - 32.5f) * dd);
        pX += expf(-dX * dX * inv2v);
    }
    red[tid] = pY; __syncthreads();
    for (int o = 128; o > 0; o >>= 1) { if (tid < o) red[tid] += red[tid + o]; __syncthreads(); }
    if (tid == 0) sc[5] = red[0];
    __syncthreads();
    red[tid] = pX; __syncthreads();
    for (int o = 128; o > 0; o >>= 1) { if (tid < o) red[tid] += red[tid + o]; __syncthreads(); }
    if (tid == 0) sc[6] = red[0];
    __syncthreads();

    float sY = gamma / sc[5];
    float sX = 1.0f / sc[6];

    // FX B-fragments
    for (int e = tid; e < 2048; e += 256) {
        int lane = e & 31, s = (e >> 5) & 7, j = e >> 8;
        int gid = lane >> 2, t4 = lane & 3;
        int m = 8 * j + gid;
        float mu = gX + ((float)m - 32.5f) * dd;
        int b0 = 16 * s + t4 * 2;
        float d0 = (float)b0 - mu,       d1 = (float)(b0 + 1) - mu;
        float d2 = (float)(b0 + 8) - mu, d3 = (float)(b0 + 9) - mu;
        float x0 = expf(-d0 * d0 * inv2v) * sX;
        float x1 = expf(-d1 * d1 * inv2v) * sX;
        float x2 = expf(-d2 * d2 * inv2v) * sX;
        float x3 = expf(-d3 * d3 * inv2v) * sX;
        uint4 v;
        v.x = prmt_hi(__float_as_uint(x0), __float_as_uint(x1));
        v.y = prmt_hi(__float_as_uint(x2), __float_as_uint(x3));
        v.z = pack_lo2(x0 - hif(x0), x1 - hif(x1));
        v.w = pack_lo2(x2 - hif(x2), x3 - hif(x3));
        g_FXfrag[e] = v;
    }

    // FY A-fragments
    for (int e = tid; e < 1024; e += 256) {
        int lane = e & 31, s = (e >> 5) & 7, r = e >> 8;
        int gid = lane >> 2, t4 = lane & 3;
        int n0 = 16 * r + gid, n1 = n0 + 8;
        float mu0 = gY + ((float)n0 - 32.5f) * dd;
        float mu1 = gY + ((float)n1 - 32.5f) * dd;
        int a0 = 16 * s + t4 * 2;
        float y[8];
        y[0] = expf(-((float)a0 - mu0)     * ((float)a0 - mu0)     * inv2v) * sY;
        y[1] = expf(-((float)(a0+1) - mu0) * ((float)(a0+1) - mu0) * inv2v) * sY;
        y[2] = expf(-((float)a0 - mu1)     * ((float)a0 - mu1)     * inv2v) * sY;
        y[3] = expf(-((float)(a0+1) - mu1) * ((float)(a0+1) - mu1) * inv2v) * sY;
        y[4] = expf(-((float)(a0+8) - mu0) * ((float)(a0+8) - mu0) * inv2v) * sY;
        y[5] = expf(-((float)(a0+9) - mu0) * ((float)(a0+9) - mu0) * inv2v) * sY;
        y[6] = expf(-((float)(a0+8) - mu1) * ((float)(a0+8) - mu1) * inv2v) * sY;
        y[7] = expf(-((float)(a0+9) - mu1) * ((float)(a0+9) - mu1) * inv2v) * sY;
        uint4 hi, lo;
        hi.x = prmt_hi(__float_as_uint(y[0]), __float_as_uint(y[1]));
        hi.y = prmt_hi(__float_as_uint(y[2]), __float_as_uint(y[3]));
        hi.z = prmt_hi(__float_as_uint(y[4]), __float_as_uint(y[5]));
        hi.w = prmt_hi(__float_as_uint(y[6]), __float_as_uint(y[7]));
        lo.x = pack_lo2(y[0] - hif(y[0]), y[1] - hif(y[1]));
        lo.y = pack_lo2(y[2] - hif(y[2]), y[3] - hif(y[3]));
        lo.z = pack_lo2(y[4] - hif(y[4]), y[5] - hif(y[5]));
        lo.w = pack_lo2(y[6] - hif(y[6]), y[7] - hif(y[7]));
        g_FYfrag[2 * e]     = hi;
        g_FYfrag[2 * e + 1] = lo;
    }
}

// ======================= device helpers =======================
__device__ __forceinline__ u32 smem_u32(const void* p) {
    u32 a;
    asm("{ .reg .u64 t; cvta.to.shared.u64 t, %1; cvt.u32.u64 %0, t; }" : "=r"(a) : "l"(p));
    return a;
}
__device__ __forceinline__ void ldm_x4(u32& r0, u32& r1, u32& r2, u32& r3, u32 addr) {
    asm volatile("ldmatrix.sync.aligned.m8n8.x4.shared.b16 {%0,%1,%2,%3}, [%4];"
                 : "=r"(r0), "=r"(r1), "=r"(r2), "=r"(r3) : "r"(addr));
}
__device__ __forceinline__ void ldm_x4t(u32& r0, u32& r1, u32& r2, u32& r3, u32 addr) {
    asm volatile("ldmatrix.sync.aligned.m8n8.x4.trans.shared.b16 {%0,%1,%2,%3}, [%4];"
                 : "=r"(r0), "=r"(r1), "=r"(r2), "=r"(r3) : "r"(addr));
}
__device__ __forceinline__ void mma_bf16(float* c, u32 a0, u32 a1, u32 a2, u32 a3, u32 b0, u32 b1) {
    asm volatile(
        "mma.sync.aligned.m16n8k16.row.col.f32.bf16.bf16.f32 "
        "{%0,%1,%2,%3}, {%4,%5,%6,%7}, {%8,%9}, {%0,%1,%2,%3};"
        : "+f"(c[0]), "+f"(c[1]), "+f"(c[2]), "+f"(c[3])
        : "r"(a0), "r"(a1), "r"(a2), "r"(a3), "r"(b0), "r"(b1));
}

// direct global load of one 32-row half-slice into registers (coalesced LDG.128)
__device__ __forceinline__ void load_v(const float* __restrict__ x,
                                       const float* __restrict__ xh,
                                       int img, int half, int tid, float* v) {
    const float* b = (img < BATCHN) ? x + (size_t)img * 16384
                                    : xh + (size_t)(img - BATCHN) * 16384;
    const float* zr = b + half * 4096 + (tid >> 3) * 128 + (tid & 7) * 16;
    *(float4*)(v)      = __ldg((const float4*)(zr));
    *(float4*)(v + 4)  = __ldg((const float4*)(zr + 4));
    *(float4*)(v + 8)  = __ldg((const float4*)(zr + 8));
    *(float4*)(v + 12) = __ldg((const float4*)(zr + 12));
}
// convert registers -> z bf16 hi/lo planes (64-row superchunk), rows offset by rbase
__device__ __forceinline__ void conv_store(char* smem, int tid, const float* v, int rbase) {
    u32 H[8], L[8];
#pragma unroll
    for (int p = 0; p < 8; p++) {
        u32 b0 = __float_as_uint(v[2 * p]), b1 = __float_as_uint(v[2 * p + 1]);
        H[p] = prmt_hi(b0, b1);
        L[p] = pack_lo2(v[2 * p]     - __uint_as_float(b0 & 0xFFFF0000u),
                        v[2 * p + 1] - __uint_as_float(b1 & 0xFFFF0000u));
    }
    int r = rbase + (tid >> 3), j8 = tid & 7;
    u32 o0 = zswz(r, 2 * j8), o1 = zswz(r, 2 * j8 + 1);
    *(uint4*)(smem + SM_Z + o0)         = make_uint4(H[0], H[1], H[2], H[3]);
    *(uint4*)(smem + SM_Z + o1)         = make_uint4(H[4], H[5], H[6], H[7]);
    *(uint4*)(smem + SM_Z + 16384 + o0) = make_uint4(L[0], L[1], L[2], L[3]);
    *(uint4*)(smem + SM_Z + 16384 + o1) = make_uint4(L[4], L[5], L[6], L[7]);
}

// ======================= main kernel =======================
__global__ void __launch_bounds__(256, 1)
main_kernel(const float* __restrict__ x, const float* __restrict__ xh,
            float* __restrict__ out, int grid) {
    extern __shared__ __align__(16) char smem[];
    int tid = threadIdx.x, wid = tid >> 5, lid = tid & 31;
    int gid = lid >> 2, t4 = lid & 3;

    u32 base = smem_u32(smem);

    // stage-1 warp mapping: aq = wid>>1 (4 a-positions of 16 rows), mq = wid&1 (m-half of 32)
    int aq = wid >> 1, mq = wid & 1;
    // ALL 4 FX j-tiles persistent in registers (no fx stream)
    uint4 fx[4][8];
#pragma unroll
    for (int j = 0; j < 4; j++)
#pragma unroll
        for (int s = 0; s < 8; s++)
            fx[j][s] = __ldg(&g_FXfrag[((4 * mq + j) * 8 + s) * 32 + lid]);

    int rowA = aq * 16 + (lid & 7) + ((lid >> 3) & 1) * 8;
    int segb = lid >> 4;
    // stage-2 mapping (x4t: lanes 0-15 -> UHI rows, 16-31 -> ULO rows)
    int r2 = wid >> 1, jh = wid & 1;
    int rowk = lid & 15, half2 = lid >> 4;
    u32 u_lane = base + (half2 ? SM_ULO : SM_UHI) + (u32)rowk * 272;

    int img0 = blockIdx.x;

    // prologue: load halves 0,1 of first image
    float v0[16], v1[16];
    if (img0 < NIMG) {
        load_v(x, xh, img0, 0, tid, v0);
        load_v(x, xh, img0, 1, tid, v1);
    }

    for (int img = img0; img < NIMG; img += grid) {

        // ================= stage 1: two 64-row superchunks =================
#pragma unroll 1
        for (int sc = 0; sc < 2; sc++) {
            // convert prefetched registers into the 64-row z planes
            conv_store(smem, tid, v0, 0);
            conv_store(smem, tid, v1, 32);
            __syncthreads();

            // prefetch next superchunk (next image's halves 0,1 when sc==1)
            {
                int nimg = (sc == 0) ? img : img + grid;
                int nh   = (sc == 0) ? 2 : 0;
                if (nimg < NIMG) {
                    load_v(x, xh, nimg, nh,     tid, v0);
                    load_v(x, xh, nimg, nh + 1, tid, v1);
                }
            }

            // ---- MMA superchunk: 16a x 32m per warp, 12 MMAs per 2 LDSM ----
            float acc[4][4];
#pragma unroll
            for (int j = 0; j < 4; j++)
#pragma unroll
                for (int q = 0; q < 4; q++) acc[j][q] = 0.f;

#pragma unroll
            for (int s = 0; s < 8; s++) {
                u32 sw = zswz(rowA, 2 * s + segb);
                u32 h0, h1, h2, h3, l0, l1, l2, l3;
                ldm_x4(h0, h1, h2, h3, base + SM_Z + sw);
                ldm_x4(l0, l1, l2, l3, base + SM_Z + 16384 + sw);
                // hh pass (RAW distance 4)
                mma_bf16(acc[0], h0, h1, h2, h3, fx[0][s].x, fx[0][s].y);
                mma_bf16(acc[1], h0, h1, h2, h3, fx[1][s].x, fx[1][s].y);
                mma_bf16(acc[2], h0, h1, h2, h3, fx[2][s].x, fx[2][s].y);
                mma_bf16(acc[3], h0, h1, h2, h3, fx[3][s].x, fx[3][s].y);
                // hl pass
                mma_bf16(acc[0], h0, h1, h2, h3, fx[0][s].z, fx[0][s].w);
                mma_bf16(acc[1], h0, h1, h2, h3, fx[1][s].z, fx[1][s].w);
                mma_bf16(acc[2], h0, h1, h2, h3, fx[2][s].z, fx[2][s].w);
                mma_bf16(acc[3], h0, h1, h2, h3, fx[3][s].z, fx[3][s].w);
                // lh pass
                mma_bf16(acc[0], l0, l1, l2, l3, fx[0][s].x, fx[0][s].y);
                mma_bf16(acc[1], l0, l1, l2, l3, fx[1][s].x, fx[1][s].y);
                mma_bf16(acc[2], l0, l1, l2, l3, fx[2][s].x, fx[2][s].y);
                mma_bf16(acc[3], l0, l1, l2, l3, fx[3][s].x, fx[3][s].y);
            }

            // ---- u epilogue: rows -> bf16 hi/lo, stride 272 B ----
            {
                int ag0 = sc * 64 + aq * 16 + gid;   // rows ag0, ag0+8
#pragma unroll
                for (int j = 0; j < 4; j++) {
                    const float* A = acc[j];
                    int m = 8 * (4 * mq + j) + t4 * 2;
                    u32 h0 = prmt_hi(__float_as_uint(A[0]), __float_as_uint(A[1]));
                    u32 l0 = pack_lo2(A[0] - hif(A[0]), A[1] - hif(A[1]));
                    u32 h1 = prmt_hi(__float_as_uint(A[2]), __float_as_uint(A[3]));
                    u32 l1 = pack_lo2(A[2] - hif(A[2]), A[3] - hif(A[3]));
                    *(u32*)(smem + SM_UHI + ag0 * 272 + m * 2)       = h0;
                    *(u32*)(smem + SM_UHI + (ag0 + 8) * 272 + m * 2) = h1;
                    *(u32*)(smem + SM_ULO + ag0 * 272 + m * 2)       = l0;
                    *(u32*)(smem + SM_ULO + (ag0 + 8) * 272 + m * 2) = l1;
                }
            }
            __syncthreads();   // z planes free for next conv; after sc==1: u complete
        }

        // ================= stage 2: out = FY @ u =================
        float a2[4][4];
#pragma unroll
        for (int jj = 0; jj < 4; jj++)
#pragma unroll
            for (int q = 0; q < 4; q++) a2[jj][q] = 0.f;

#pragma unroll
        for (int s = 0; s < 8; s++) {
            uint4 fyh = __ldg(&g_FYfrag[((r2 * 8 + s) * 32 + lid) * 2]);
            uint4 fyl = __ldg(&g_FYfrag[((r2 * 8 + s) * 32 + lid) * 2 + 1]);
            u32 soff = (u32)(s * 16 * 272);
#pragma unroll
            for (int jj = 0; jj < 4; jj++) {
                int j = jh * 4 + jj;
                u32 bh0, bh1, bl0, bl1;
                ldm_x4t(bh0, bh1, bl0, bl1, u_lane + soff + j * 16);
                mma_bf16(a2[jj], fyh.x, fyh.y, fyh.z, fyh.w, bh0, bh1);   // hh
                mma_bf16(a2[jj], fyh.x, fyh.y, fyh.z, fyh.w, bl0, bl1);   // hl
                mma_bf16(a2[jj], fyl.x, fyl.y, fyl.z, fyl.w, bh0, bh1);   // lh
            }
        }

        // ---- write out ----
        size_t obase = (img < BATCHN) ? (size_t)img * 8192
                                      : (size_t)(img - BATCHN) * 8192 + 4096;
        float* op = out + obase;
        int n0 = 16 * r2 + gid;
#pragma unroll
        for (int jj = 0; jj < 4; jj++) {
            int m = 8 * (jh * 4 + jj) + t4 * 2;
            float2 w0; w0.x = a2[jj][0]; w0.y = a2[jj][1];
            float2 w1; w1.x = a2[jj][2]; w1.y = a2[jj][3];
            *(float2*)(op + (size_t)n0 * 64 + m)       = w0;
            *(float2*)(op + (size_t)(n0 + 8) * 64 + m) = w1;
        }
        __syncthreads();   // u free before next image's stage-1 u-stores
    }
}

// ======================= launch =======================
extern "C" void kernel_launch(void* const* d_in, const int* in_sizes, int n_in,
                              void* d_out, int out_size) {
    const float* x  = (const float*)d_in[0];
    const float* xh = (const float*)d_in[1];
    const float* h  = (const float*)d_in[2];
    const float* W  = (const float*)d_in[3];
    const float* b  = (const float*)d_in[4];
    float* out = (float*)d_out;

    setup_kernel<<<1, 256>>>(h, W, b);

    cudaFuncSetAttribute(main_kernel, cudaFuncAttributeMaxDynamicSharedMemorySize, SMEM_TOTAL);

    int dev = 0, sm = 148;
    cudaGetDevice(&dev);
    cudaDeviceGetAttribute(&sm, cudaDevAttrMultiProcessorCount, dev);
    int grid = sm;
    if (grid < 1) grid = 148;
    if (grid > NIMG) grid = NIMG;

    main_kernel<<<grid, 256, SMEM_TOTAL>>>(x, xh, out, grid);
}